// round 14
// baseline (speedup 1.0000x reference)
#include <cuda_runtime.h>
#include <cstdint>

// MultiHeadAttention_5128190951704 — algebraic collapse:
//   softmax rows sum to 1 and 'bnqk,bnvd->bnqd' is separable in k/v, so
//   y[b,o,d] = b_proj[o] + sum_n wp_sum[o,n] * sum_c wv_sum[n,c] * x[b,c,d]
// Rank-8 channel map per position. Memory-bound: 256 MB ideal traffic.
//
// R11 restructure: c-split across 4 groups per block for 4x occupancy + MLP.

#define B_   16
#define C_   512
#define NH_  8
#define S_   4096          // H*W
#define TPB  256
#define G_   4             // channel groups per block
#define GSZ  64            // threads per group
#define P_   128           // positions per block (2 per thread)
#define CPG  128           // channels per group
#define REDP 10            // padded reduction row (ulls): 80B, LDS.128-aligned, conflict-free

typedef unsigned long long ull;

// Folded weights (alloc-free rule: __device__ globals)
__device__ ull   g_wv2[C_ * NH_];   // [c][n], value duplicated into both f32 halves
__device__ float g_wp [C_ * NH_];   // [o][n]

__device__ __forceinline__ ull dup2(float v) {
    ull r;
    asm("mov.b64 %0, {%1, %1};" : "=l"(r) : "r"(__float_as_uint(v)));
    return r;
}
__device__ __forceinline__ ull fma2(ull a, ull b, ull c) {
    ull d;
    asm("fma.rn.f32x2 %0, %1, %2, %3;" : "=l"(d) : "l"(a), "l"(b), "l"(c));
    return d;
}
__device__ __forceinline__ ull add2(ull a, ull b) {
    ull d;
    asm("add.rn.f32x2 %0, %1, %2;" : "=l"(d) : "l"(a), "l"(b));
    return d;
}

// ---------------------------------------------------------------------------
// Prep: fold weights (8192 sums of 64 terms, ~1 MB reads, trivial cost).
// ---------------------------------------------------------------------------
__global__ void prep_kernel(const float* __restrict__ wqkv,
                            const float* __restrict__ wproj) {
    int t = blockIdx.x * blockDim.x + threadIdx.x;
    if (t < NH_ * C_) {
        // wv_sum[n][c] = sum_j wqkv[2C + n*64 + j][c], stored [c][n] dup'd
        int n = t >> 9, c = t & (C_ - 1);
        const float* p = wqkv + (size_t)(2 * C_ + n * 64) * C_ + c;
        float s = 0.f;
        #pragma unroll
        for (int j = 0; j < 64; j++) s += p[(size_t)j * C_];
        g_wv2[c * NH_ + n] = dup2(s);
    } else if (t < 2 * NH_ * C_) {
        // wp_sum[o][n] = sum_j wproj[o][n*64 + j]
        int u = t - NH_ * C_;
        int o = u >> 3, n = u & 7;
        const float* p = wproj + (size_t)o * C_ + n * 64;
        float s = 0.f;
        #pragma unroll
        for (int j = 0; j < 64; j++) s += p[j];
        g_wp[o * NH_ + n] = s;
    }
}

// ---------------------------------------------------------------------------
// Main kernel: 512 blocks x 256 threads.
// Group g (64 threads) phase1: channels [g*128, g*128+128) of the block's
// 128 positions; SMEM reduction of the 8 packed accumulators; phase2:
// output channels [g*128, g*128+128).
// SMEM: wv2 32KB | red 20KB | wp 16KB | bias 2KB = 70KB -> 3 CTAs/SM.
// ---------------------------------------------------------------------------
#define SMEM_ULLS  (C_ * NH_ + G_ * GSZ * REDP)          // 4096 + 2560
#define SMEM_BYTES (SMEM_ULLS * 8 + (C_ * NH_ + C_) * 4) // 71680

__global__ void __launch_bounds__(TPB, 3)
attn_main(const float* __restrict__ x,
          const float* __restrict__ bias,
          float* __restrict__ y) {
    extern __shared__ ull smem[];
    ull*   s_wv2 = smem;                         // [c][n] packed, 4096 ull
    ull*   s_red = smem + C_ * NH_;              // [g][tg][n(+pad)], 2560 ull
    float* s_wp  = (float*)(smem + SMEM_ULLS);   // [o][n], 4096 f
    float* s_b   = s_wp + C_ * NH_;              // [o], 512 f

    const int tid = threadIdx.x;
    for (int t = tid; t < C_ * NH_; t += TPB) {
        s_wv2[t] = g_wv2[t];
        s_wp[t]  = g_wp[t];
    }
    for (int t = tid; t < C_; t += TPB) s_b[t] = bias[t];
    __syncthreads();

    const int b     = blockIdx.x >> 5;           // 16 batches
    const int tile  = blockIdx.x & 31;           // 32 tiles of 128 positions
    const int dhalf = (tile * P_) >> 1;          // pair-index base
    const int g     = tid >> 6;                  // channel/output group
    const int tg    = tid & (GSZ - 1);           // position-pair owner

    // ---- Phase 1: partial acc over this group's 128 channels ----
    const ull* xp = (const ull*)x + (size_t)(b * C_ + g * CPG) * (S_ / 2)
                    + dhalf + tg;
    ull acc[NH_];
    #pragma unroll
    for (int n = 0; n < NH_; n++) acc[n] = 0ull;

    #pragma unroll 8
    for (int cc = 0; cc < CPG; cc++) {
        ull xv = xp[(size_t)cc * (S_ / 2)];      // coalesced, 8 in flight
        const ulonglong2* wv =
            (const ulonglong2*)(s_wv2 + (g * CPG + cc) * NH_);
        ulonglong2 w0 = wv[0], w1 = wv[1], w2 = wv[2], w3 = wv[3];
        acc[0] = fma2(w0.x, xv, acc[0]);
        acc[1] = fma2(w0.y, xv, acc[1]);
        acc[2] = fma2(w1.x, xv, acc[2]);
        acc[3] = fma2(w1.y, xv, acc[3]);
        acc[4] = fma2(w2.x, xv, acc[4]);
        acc[5] = fma2(w2.y, xv, acc[5]);
        acc[6] = fma2(w3.x, xv, acc[6]);
        acc[7] = fma2(w3.y, xv, acc[7]);
    }

    // ---- Cross-group reduction through padded SMEM ----
    {
        ull* r = s_red + (g * GSZ + tg) * REDP;
        #pragma unroll
        for (int n = 0; n < NH_; n += 2)
            *(ulonglong2*)(r + n) = make_ulonglong2(acc[n], acc[n + 1]);
    }
    __syncthreads();

    ull tot[NH_];
    #pragma unroll
    for (int n = 0; n < NH_; n++) tot[n] = 0ull;
    #pragma unroll
    for (int gg = 0; gg < G_; gg++) {
        const ull* r = s_red + (gg * GSZ + tg) * REDP;
        #pragma unroll
        for (int n = 0; n < NH_; n += 2) {
            ulonglong2 v = *(const ulonglong2*)(r + n);
            tot[n]     = add2(tot[n], v.x);
            tot[n + 1] = add2(tot[n + 1], v.y);
        }
    }

    // ---- Phase 2: this group's 128 output channels ----
    ull* yp = (ull*)y + (size_t)(b * C_ + g * CPG) * (S_ / 2) + dhalf + tg;
    #pragma unroll 4
    for (int oo = 0; oo < CPG; oo++) {
        const int o = g * CPG + oo;
        const float4* wp = (const float4*)(s_wp + o * NH_);
        float4 wa = wp[0], wb = wp[1];
        ull r = dup2(s_b[o]);
        r = fma2(dup2(wa.x), tot[0], r);
        r = fma2(dup2(wa.y), tot[1], r);
        r = fma2(dup2(wa.z), tot[2], r);
        r = fma2(dup2(wa.w), tot[3], r);
        r = fma2(dup2(wb.x), tot[4], r);
        r = fma2(dup2(wb.y), tot[5], r);
        r = fma2(dup2(wb.z), tot[6], r);
        r = fma2(dup2(wb.w), tot[7], r);
        yp[(size_t)oo * (S_ / 2)] = r;           // coalesced STG.64
    }
}

// ---------------------------------------------------------------------------
extern "C" void kernel_launch(void* const* d_in, const int* in_sizes, int n_in,
                              void* d_out, int out_size) {
    const float* x     = (const float*)d_in[0];
    const float* wqkv  = (const float*)d_in[1];
    const float* wproj = (const float*)d_in[2];
    const float* bproj = (const float*)d_in[3];
    float* y = (float*)d_out;

    cudaFuncSetAttribute(attn_main, cudaFuncAttributeMaxDynamicSharedMemorySize,
                         SMEM_BYTES);

    prep_kernel<<<32, 256>>>(wqkv, wproj);
    attn_main<<<B_ * (S_ / P_), TPB, SMEM_BYTES>>>(x, bproj, y);
}

// round 15
// speedup vs baseline: 1.1116x; 1.1116x over previous
#include <cuda_runtime.h>
#include <cstdint>

// MultiHeadAttention_5128190951704 — algebraic collapse:
//   softmax rows sum to 1 and 'bnqk,bnvd->bnqd' is separable in k/v, so
//   y[b,o,d] = b_proj[o] + sum_n wp_sum[o,n] * sum_c wv_sum[n,c] * x[b,c,d]
// Rank-8 channel map per position. Memory floor: 256 MB => ~37 us.
//
// R14->R17: LDG.128/STG.128 (4 positions per thread), doubled in-flight
// bytes per warp; wp pre-duplicated for FFMA2; 2 CTAs/SM @ 104KB SMEM.

#define B_   16
#define C_   512
#define NH_  8
#define S_   4096          // H*W
#define TPB  256
#define G_   4             // channel groups per block
#define GSZ  64            // threads per group
#define P_   256           // positions per block (4 per thread)
#define CPG  128           // channels per group
#define REDP 18            // padded reduction row in ulls (16B-aligned)

typedef unsigned long long ull;

// Folded weights (alloc-free rule: __device__ globals), f32x2-duplicated
__device__ ull g_wv2[C_ * NH_];   // [c][n]
__device__ ull g_wp2[C_ * NH_];   // [o][n]

__device__ __forceinline__ ull dup2(float v) {
    ull r;
    asm("mov.b64 %0, {%1, %1};" : "=l"(r) : "r"(__float_as_uint(v)));
    return r;
}
__device__ __forceinline__ ull fma2(ull a, ull b, ull c) {
    ull d;
    asm("fma.rn.f32x2 %0, %1, %2, %3;" : "=l"(d) : "l"(a), "l"(b), "l"(c));
    return d;
}
__device__ __forceinline__ ull add2(ull a, ull b) {
    ull d;
    asm("add.rn.f32x2 %0, %1, %2;" : "=l"(d) : "l"(a), "l"(b));
    return d;
}

// ---------------------------------------------------------------------------
// Prep: fold weights (8192 sums of 64 terms; ~2 MB reads, trivial cost).
// ---------------------------------------------------------------------------
__global__ void prep_kernel(const float* __restrict__ wqkv,
                            const float* __restrict__ wproj) {
    int t = blockIdx.x * blockDim.x + threadIdx.x;
    if (t < NH_ * C_) {
        // wv_sum[n][c] = sum_j wqkv[2C + n*64 + j][c], stored [c][n] dup'd
        int n = t >> 9, c = t & (C_ - 1);
        const float* p = wqkv + (size_t)(2 * C_ + n * 64) * C_ + c;
        float s = 0.f;
        #pragma unroll
        for (int j = 0; j < 64; j++) s += p[(size_t)j * C_];
        g_wv2[c * NH_ + n] = dup2(s);
    } else if (t < 2 * NH_ * C_) {
        // wp_sum[o][n] = sum_j wproj[o][n*64 + j], stored [o][n] dup'd
        int u = t - NH_ * C_;
        int o = u >> 3, n = u & 7;
        const float* p = wproj + (size_t)o * C_ + n * 64;
        float s = 0.f;
        #pragma unroll
        for (int j = 0; j < 64; j++) s += p[j];
        g_wp2[o * NH_ + n] = s >= 0.f || s < 0.f ? dup2(s) : dup2(s);
    }
}

// ---------------------------------------------------------------------------
// Main kernel: 256 blocks x 256 threads, 2 CTAs/SM.
// Group g (64 threads): phase1 over channels [g*128, g*128+128) for the
// block's 256 positions (4/thread, LDG.128); SMEM reduction; phase2 over
// output channels [g*128, g*128+128) (STG.128).
// SMEM ulls: wv2 4096 | wp2 4096 | bias 512 | red 256*18=4608  -> 104 KB.
// ---------------------------------------------------------------------------
#define SMEM_ULLS  (2 * C_ * NH_ + C_ + TPB * REDP)
#define SMEM_BYTES (SMEM_ULLS * 8)   // 106496 = 104 KB

__global__ void __launch_bounds__(TPB, 2)
attn_main(const float* __restrict__ x,
          const float* __restrict__ bias,
          float* __restrict__ y) {
    extern __shared__ ull smem[];
    ull* s_wv2 = smem;                       // [c][n] dup'd
    ull* s_wp2 = smem + C_ * NH_;            // [o][n] dup'd
    ull* s_b2  = smem + 2 * C_ * NH_;        // [o] dup'd
    ull* s_red = smem + 2 * C_ * NH_ + C_;   // [thread][16 + pad]

    const int tid = threadIdx.x;
    for (int t = tid; t < C_ * NH_; t += TPB) {
        s_wv2[t] = g_wv2[t];
        s_wp2[t] = g_wp2[t];
    }
    for (int t = tid; t < C_; t += TPB) s_b2[t] = dup2(bias[t]);
    __syncthreads();

    const int b    = blockIdx.x >> 4;        // 16 batches
    const int tile = blockIdx.x & 15;        // 16 tiles of 256 positions
    const int g    = tid >> 6;               // channel/output group
    const int tg   = tid & (GSZ - 1);        // position-quad owner
    const int qoff = tile * (P_ / 4) + tg;   // quad index within row

    // ---- Phase 1: partial acc over this group's 128 channels ----
    const ulonglong2* xp = (const ulonglong2*)x
        + (size_t)(b * C_ + g * CPG) * (S_ / 4) + qoff;
    ull a0[NH_], a1[NH_];                    // positions {0,1} and {2,3}
    #pragma unroll
    for (int n = 0; n < NH_; n++) { a0[n] = 0ull; a1[n] = 0ull; }

    #pragma unroll 8
    for (int cc = 0; cc < CPG; cc++) {
        ulonglong2 xv = xp[(size_t)cc * (S_ / 4)];   // LDG.128, coalesced
        const ulonglong2* wv =
            (const ulonglong2*)(s_wv2 + (g * CPG + cc) * NH_);
        ulonglong2 w0 = wv[0], w1 = wv[1], w2 = wv[2], w3 = wv[3];
        a0[0] = fma2(w0.x, xv.x, a0[0]);  a1[0] = fma2(w0.x, xv.y, a1[0]);
        a0[1] = fma2(w0.y, xv.x, a0[1]);  a1[1] = fma2(w0.y, xv.y, a1[1]);
        a0[2] = fma2(w1.x, xv.x, a0[2]);  a1[2] = fma2(w1.x, xv.y, a1[2]);
        a0[3] = fma2(w1.y, xv.x, a0[3]);  a1[3] = fma2(w1.y, xv.y, a1[3]);
        a0[4] = fma2(w2.x, xv.x, a0[4]);  a1[4] = fma2(w2.x, xv.y, a1[4]);
        a0[5] = fma2(w2.y, xv.x, a0[5]);  a1[5] = fma2(w2.y, xv.y, a1[5]);
        a0[6] = fma2(w3.x, xv.x, a0[6]);  a1[6] = fma2(w3.x, xv.y, a1[6]);
        a0[7] = fma2(w3.y, xv.x, a0[7]);  a1[7] = fma2(w3.y, xv.y, a1[7]);
    }

    // ---- Cross-group reduction through padded SMEM ----
    {
        ull* r = s_red + tid * REDP;
        #pragma unroll
        for (int n = 0; n < NH_; n += 2) {
            *(ulonglong2*)(r + 2 * n)     = make_ulonglong2(a0[n], a0[n + 1]);
            *(ulonglong2*)(r + 2 * n + 2) = make_ulonglong2(a1[n], a1[n + 1]);
        }
    }
    __syncthreads();

    ull t0[NH_], t1[NH_];
    #pragma unroll
    for (int n = 0; n < NH_; n++) { t0[n] = 0ull; t1[n] = 0ull; }
    #pragma unroll
    for (int gg = 0; gg < G_; gg++) {
        const ull* r = s_red + (gg * GSZ + tg) * REDP;
        #pragma unroll
        for (int n = 0; n < NH_; n += 2) {
            ulonglong2 v0 = *(const ulonglong2*)(r + 2 * n);
            ulonglong2 v1 = *(const ulonglong2*)(r + 2 * n + 2);
            t0[n]     = add2(t0[n],     v0.x);
            t0[n + 1] = add2(t0[n + 1], v0.y);
            t1[n]     = add2(t1[n],     v1.x);
            t1[n + 1] = add2(t1[n + 1], v1.y);
        }
    }

    // ---- Phase 2: this group's 128 output channels, STG.128 ----
    ulonglong2* yp = (ulonglong2*)y
        + (size_t)(b * C_ + g * CPG) * (S_ / 4) + qoff;
    #pragma unroll 4
    for (int oo = 0; oo < CPG; oo++) {
        const int o = g * CPG + oo;
        const ulonglong2* wp = (const ulonglong2*)(s_wp2 + o * NH_);
        ulonglong2 w0 = wp[0], w1 = wp[1], w2 = wp[2], w3 = wp[3];
        ull bb = s_b2[o];
        ull r0 = bb, r1 = bb;
        r0 = fma2(w0.x, t0[0], r0);  r1 = fma2(w0.x, t1[0], r1);
        r0 = fma2(w0.y, t0[1], r0);  r1 = fma2(w0.y, t1[1], r1);
        r0 = fma2(w1.x, t0[2], r0);  r1 = fma2(w1.x, t1[2], r1);
        r0 = fma2(w1.y, t0[3], r0);  r1 = fma2(w1.y, t1[3], r1);
        r0 = fma2(w2.x, t0[4], r0);  r1 = fma2(w2.x, t1[4], r1);
        r0 = fma2(w2.y, t0[5], r0);  r1 = fma2(w2.y, t1[5], r1);
        r0 = fma2(w3.x, t0[6], r0);  r1 = fma2(w3.x, t1[6], r1);
        r0 = fma2(w3.y, t0[7], r0);  r1 = fma2(w3.y, t1[7], r1);
        yp[(size_t)oo * (S_ / 4)] = make_ulonglong2(r0, r1);  // STG.128
    }
}

// ---------------------------------------------------------------------------
extern "C" void kernel_launch(void* const* d_in, const int* in_sizes, int n_in,
                              void* d_out, int out_size) {
    const float* x     = (const float*)d_in[0];
    const float* wqkv  = (const float*)d_in[1];
    const float* wproj = (const float*)d_in[2];
    const float* bproj = (const float*)d_in[3];
    float* y = (float*)d_out;

    cudaFuncSetAttribute(attn_main, cudaFuncAttributeMaxDynamicSharedMemorySize,
                         SMEM_BYTES);

    prep_kernel<<<32, 256>>>(wqkv, wproj);
    attn_main<<<B_ * (S_ / P_), TPB, SMEM_BYTES>>>(x, bproj, y);
}